// round 13
// baseline (speedup 1.0000x reference)
#include <cuda_runtime.h>
#include <cstdint>

#define HW    3136
#define CIN   1024
#define NT    224      // 14 * 224 = 3136 exactly
#define KC    64       // k chunk (4 chunks of 64)
#define NCH   4

// smem floats: A: 2 stages of [128 m][pitch 68]  (raw fp32, rna at fragment load)
//              B: 2 stages of [64 k][pitch 232]
#define APITCH  68
#define ASZ     (128 * APITCH)          // 8704
#define BOFF    (2 * ASZ)               // 17408
#define BPITCH  232
#define BSZ     (KC * BPITCH)           // 14848
#define SM_FLOATS (BOFF + 2 * BSZ)      // 47104
#define SM_BYTES  (SM_FLOATS * 4)       // 188416

static __device__ __forceinline__ float rna_f(float v) {
    uint32_t o;
    asm("cvt.rna.tf32.f32 %0, %1;" : "=r"(o) : "f"(v));
    return __uint_as_float(o);
}
static __device__ __forceinline__ uint32_t smem_u32(const void* p) {
    uint32_t a;
    asm("{\n\t.reg .u64 t;\n\tcvta.to.shared.u64 t, %1;\n\tcvt.u32.u64 %0, t;\n\t}"
        : "=r"(a) : "l"(p));
    return a;
}
static __device__ __forceinline__ void cp16(uint32_t dst, const void* src) {
    asm volatile("cp.async.cg.shared.global [%0], [%1], 16;" :: "r"(dst), "l"(src) : "memory");
}
static __device__ __forceinline__ void cp_commit() {
    asm volatile("cp.async.commit_group;" ::: "memory");
}
template <int N>
static __device__ __forceinline__ void cp_wait() {
    asm volatile("cp.async.wait_group %0;" :: "n"(N) : "memory");
}

static __device__ __forceinline__ void mma8(float* c, const float* a, const float* b) {
    asm volatile(
        "mma.sync.aligned.m16n8k8.row.col.f32.tf32.tf32.f32 "
        "{%0,%1,%2,%3}, {%4,%5,%6,%7}, {%8,%9}, {%0,%1,%2,%3};"
        : "+f"(c[0]), "+f"(c[1]), "+f"(c[2]), "+f"(c[3])
        : "r"(__float_as_uint(a[0])), "r"(__float_as_uint(a[1])),
          "r"(__float_as_uint(a[2])), "r"(__float_as_uint(a[3])),
          "r"(__float_as_uint(b[0])), "r"(__float_as_uint(b[1])));
}

__global__ __launch_bounds__(256, 1)
void scc_mma_kernel(const float* __restrict__ x,
                    const float* __restrict__ w,
                    float* __restrict__ out)
{
    extern __shared__ float sm[];
    const uint32_t sb = smem_u32(sm);
    const int tid = threadIdx.x;
    const int lid = tid & 31, wid = tid >> 5;
    const int g = lid >> 2, tg = lid & 3;
    const int r  = blockIdx.x;                 // group fastest: L2 x reuse
    const int p0 = blockIdx.y * NT;
    const int b  = blockIdx.z;
    const float* xb = x + (size_t)b * CIN * HW;

    // warp grid 2(M) x 4(N): warp tile 64 x 56
    const int m0 = (wid & 1) * 64;
    const int n0 = (wid >> 1) * 56;

    float acc[4][7][4];
    #pragma unroll
    for (int i = 0; i < 4; i++)
        #pragma unroll
        for (int j = 0; j < 7; j++)
            #pragma unroll
            for (int v = 0; v < 4; v++) acc[i][j][v] = 0.f;

    // ---- chunk loader: A (8 cp16/thread) + B (14 cp16/thread), one commit group
    auto ISSUE = [&](int ch, int stage) {
        // A: idx = tid + 256*it (it 0..7) -> m = idx/16, q = idx%16
        const uint32_t abase = sb + (stage * ASZ) * 4;
        const float* wsrc = w + (size_t)r * 256 + ch * KC;
        #pragma unroll
        for (int it = 0; it < 8; it++) {
            const int idx = tid + 256 * it;
            const int m = idx >> 4, q = idx & 15;
            cp16(abase + (m * APITCH + 4 * q) * 4,
                 wsrc + (size_t)(8 * m) * 256 + 4 * q);
        }
        // B: idx = tid + 256*it (it 0..13) -> k = idx/56, nq = idx%56
        const int c0 = (r * 128 + ch * KC) & (CIN - 1);
        const uint32_t bbase = sb + (BOFF + stage * BSZ) * 4;
        #pragma unroll
        for (int it = 0; it < 14; it++) {
            const int idx = tid + 256 * it;
            const int k = idx / 56, nq = idx % 56;
            cp16(bbase + (k * BPITCH + 4 * nq) * 4,
                 xb + (size_t)(c0 + k) * HW + p0 + 4 * nq);
        }
        cp_commit();
    };

    auto COMPUTE = [&](int stage) {
        const float* Ab = sm + stage * ASZ;           // [m][68] raw fp32
        const float* Bb = sm + BOFF + stage * BSZ;    // [k][232]
        float af[2][4][4], bf[2][7][2];

        auto LOADFRAG = [&](int kk, int buf) {
            const int kb = kk * 8;
            #pragma unroll
            for (int i = 0; i < 4; i++) {
                const float* lo = Ab + (m0 + 16 * i + g) * APITCH + kb + tg;
                const float* hi = lo + 8 * APITCH;
                af[buf][i][0] = rna_f(lo[0]);
                af[buf][i][1] = rna_f(hi[0]);
                af[buf][i][2] = rna_f(lo[4]);
                af[buf][i][3] = rna_f(hi[4]);
            }
            #pragma unroll
            for (int j = 0; j < 7; j++) {
                const int n = n0 + 8 * j + g;
                bf[buf][j][0] = Bb[(kb + tg) * BPITCH + n];
                bf[buf][j][1] = Bb[(kb + tg + 4) * BPITCH + n];
            }
        };

        LOADFRAG(0, 0);
        #pragma unroll
        for (int kk = 0; kk < 8; kk++) {
            const int cur = kk & 1;
            if (kk + 1 < 8) LOADFRAG(kk + 1, cur ^ 1);   // prefetch next fragments
            #pragma unroll
            for (int i = 0; i < 4; i++)
                #pragma unroll
                for (int j = 0; j < 7; j++)
                    mma8(acc[i][j], af[cur][i], bf[cur][j]);
        }
    };

    // ---- mainloop: 2-stage, loads overlap a full chunk of compute ----
    ISSUE(0, 0);
    ISSUE(1, 1);
    cp_wait<1>();
    __syncthreads();

    #pragma unroll 1
    for (int ch = 0; ch < NCH; ch++) {
        COMPUTE(ch & 1);
        if (ch + 1 < NCH) {
            cp_wait<0>();              // chunk ch+1 landed (issued a full compute ago)
            __syncthreads();           // also frees stage (ch&1) for reuse
            if (ch + 2 < NCH) ISSUE(ch + 2, ch & 1);
        }
    }

    // ---- epilogue: direct STG, float2 halves (full 32B sectors across quads) ----
    float* ob = out + ((size_t)b * 1024 + r) * HW + p0 + n0 + 2 * tg;
    #pragma unroll
    for (int i = 0; i < 4; i++) {
        const int mlo = m0 + 16 * i + g;
        float* prow = ob + (size_t)(8 * mlo) * HW;
        #pragma unroll
        for (int j = 0; j < 7; j++) {
            *(float2*)(prow + 8 * j) = make_float2(acc[i][j][0], acc[i][j][1]);
            *(float2*)(prow + (size_t)64 * HW + 8 * j) = make_float2(acc[i][j][2], acc[i][j][3]);
        }
    }
}

extern "C" void kernel_launch(void* const* d_in, const int* in_sizes, int n_in,
                              void* d_out, int out_size)
{
    const float* x = (const float*)d_in[0];
    const float* w = (const float*)d_in[1];
    float* out = (float*)d_out;

    cudaFuncSetAttribute(scc_mma_kernel,
                         cudaFuncAttributeMaxDynamicSharedMemorySize, SM_BYTES);
    dim3 grid(8, 14, 16);   // r fastest: adjacent groups share x channels in L2
    scc_mma_kernel<<<grid, 256, SM_BYTES>>>(x, w, out);
}

// round 14
// speedup vs baseline: 1.0403x; 1.0403x over previous
#include <cuda_runtime.h>
#include <cstdint>

#define HW    3136
#define CIN   1024
#define NT    224      // 14 * 224 = 3136 exactly
#define KC    32
#define NCH   8

// smem (floats): A: 2 buffers of 4 kk-octets x 128 m x 8 (pre-swizzled image)
//                B: 2 buffers of [32 k][pitch 232]
#define ASZ     4096
#define BOFF    (2 * ASZ)              // 8192
#define BPITCH  232
#define BSZ     (KC * BPITCH)          // 7424
#define SM_FLOATS (BOFF + 2 * BSZ)     // 23040
#define SM_BYTES  (SM_FLOATS * 4)      // 92160

// pre-rounded, pre-swizzled weights: [r(8)][ch(8)][octet(4)][m(128)][8 floats]
__device__ float g_wtf[8 * 8 * 4096];

static __device__ __forceinline__ float rna_f(float v) {
    uint32_t o;
    asm("cvt.rna.tf32.f32 %0, %1;" : "=r"(o) : "f"(v));
    return __uint_as_float(o);
}
static __device__ __forceinline__ uint32_t smem_u32(const void* p) {
    uint32_t a;
    asm("{\n\t.reg .u64 t;\n\tcvta.to.shared.u64 t, %1;\n\tcvt.u32.u64 %0, t;\n\t}"
        : "=r"(a) : "l"(p));
    return a;
}
static __device__ __forceinline__ void cp16(uint32_t dst, const void* src) {
    asm volatile("cp.async.cg.shared.global [%0], [%1], 16;" :: "r"(dst), "l"(src) : "memory");
}
static __device__ __forceinline__ void cp_commit() {
    asm volatile("cp.async.commit_group;" ::: "memory");
}
template <int N>
static __device__ __forceinline__ void cp_wait() {
    asm volatile("cp.async.wait_group %0;" :: "n"(N) : "memory");
}

static __device__ __forceinline__ void mma8(float* c, const float* a, const float* b) {
    asm volatile(
        "mma.sync.aligned.m16n8k8.row.col.f32.tf32.tf32.f32 "
        "{%0,%1,%2,%3}, {%4,%5,%6,%7}, {%8,%9}, {%0,%1,%2,%3};"
        : "+f"(c[0]), "+f"(c[1]), "+f"(c[2]), "+f"(c[3])
        : "r"(__float_as_uint(a[0])), "r"(__float_as_uint(a[1])),
          "r"(__float_as_uint(a[2])), "r"(__float_as_uint(a[3])),
          "r"(__float_as_uint(b[0])), "r"(__float_as_uint(b[1])));
}

// ---- prepass: round w and lay it out in the exact smem A image ----
// pair id q: p2 = q&3 (pair slot), m = (q>>2)&127, o = (q>>9)&3, ch = (q>>11)&7, r = q>>14
// slot p2 holds k-values c = p2 ^ ((m>>2)&3) and c+4 (of octet o) for row (r + 8m).
__global__ void scc_prep_w(const float* __restrict__ w)
{
    const int q = blockIdx.x * 256 + threadIdx.x;   // 0 .. 131071
    const int p2 = q & 3;
    const int m  = (q >> 2) & 127;
    const int o  = (q >> 9) & 3;
    const int ch = (q >> 11) & 7;
    const int r  = q >> 14;
    const int c  = p2 ^ ((m >> 2) & 3);
    const float* row = w + (size_t)(r + 8 * m) * 256 + ch * KC + o * 8;
    *(float2*)(g_wtf + 2 * (size_t)q) = make_float2(rna_f(row[c]), rna_f(row[c + 4]));
}

__global__ __launch_bounds__(256, 1)
void scc_mma_kernel(const float* __restrict__ x,
                    float* __restrict__ out)
{
    extern __shared__ float sm[];
    const uint32_t sb = smem_u32(sm);
    const int tid = threadIdx.x;
    const int lid = tid & 31, wid = tid >> 5;
    const int g = lid >> 2, tg = lid & 3;
    const int r  = blockIdx.x;                 // group fastest: L2 x reuse
    const int p0 = blockIdx.y * NT;
    const int b  = blockIdx.z;
    const float* xb = x + (size_t)b * CIN * HW;

    // warp grid 2(M) x 4(N): warp tile 64 x 56
    const int m0 = (wid & 1) * 64;
    const int n0 = (wid >> 1) * 56;

    float acc[4][7][4];
    #pragma unroll
    for (int i = 0; i < 4; i++)
        #pragma unroll
        for (int j = 0; j < 7; j++)
            #pragma unroll
            for (int v = 0; v < 4; v++) acc[i][j][v] = 0.f;

    // ---- chunk loader: A = contiguous 16KB image copy; B = 7 x cp16 ----
    auto ISSUE = [&](int ch, int buf) {
        const float* asrc = g_wtf + (size_t)(r * 8 + ch) * ASZ;
        const uint32_t abase = sb + (buf * ASZ) * 4;
        #pragma unroll
        for (int it = 0; it < 4; it++) {
            const int f4 = tid + 256 * it;               // float4 id 0..1023
            cp16(abase + f4 * 16, asrc + 4 * f4);
        }
        const int c0 = (r * 128 + ch * KC) & (CIN - 1);
        const uint32_t bbase = sb + (BOFF + buf * BSZ) * 4;
        #pragma unroll
        for (int it = 0; it < 7; it++) {
            const int idx = tid + 256 * it;
            const int k = idx / 56, nq = idx % 56;
            cp16(bbase + (k * BPITCH + 4 * nq) * 4,
                 xb + (size_t)(c0 + k) * HW + p0 + 4 * nq);
        }
        cp_commit();
    };

    auto COMPUTE = [&](int buf) {
        const float* Ab = sm + buf * ASZ;
        const float* Bb = sm + BOFF + buf * BSZ;
        #pragma unroll
        for (int kk = 0; kk < 4; kk++) {
            const float* Abk = Ab + kk * 1024;
            const float* Bbk = Bb + kk * 8 * BPITCH;
            float af[4][4], bf[7][2];
            #pragma unroll
            for (int i = 0; i < 4; i++) {
                const int rlo = m0 + 16 * i + g;
                const int rhi = rlo + 8;
                const float2 lo = *(const float2*)(Abk + rlo * 8 + ((2 * tg) ^ (2 * ((rlo >> 2) & 3))));
                const float2 hi = *(const float2*)(Abk + rhi * 8 + ((2 * tg) ^ (2 * ((rhi >> 2) & 3))));
                af[i][0] = lo.x; af[i][1] = hi.x; af[i][2] = lo.y; af[i][3] = hi.y;
            }
            #pragma unroll
            for (int j = 0; j < 7; j++) {
                const int n = n0 + 8 * j + g;
                bf[j][0] = Bbk[tg * BPITCH + n];
                bf[j][1] = Bbk[(tg + 4) * BPITCH + n];
            }
            #pragma unroll
            for (int i = 0; i < 4; i++)
                #pragma unroll
                for (int j = 0; j < 7; j++)
                    mma8(acc[i][j], af[i], bf[j]);
        }
    };

    // ---- pipelined mainloop (R5 structure, all loads async) ----
    ISSUE(0, 0);
    cp_wait<0>();
    __syncthreads();

    #pragma unroll 1
    for (int ch = 0; ch < NCH; ch++) {
        const int buf = ch & 1;
        if (ch + 1 < NCH) ISSUE(ch + 1, buf ^ 1);   // overlaps compute below
        COMPUTE(buf);
        if (ch + 1 < NCH) {
            cp_wait<0>();
            __syncthreads();
        }
    }

    // ---- epilogue: direct STG, float2 halves (full 32B sectors across quads) ----
    float* ob = out + ((size_t)b * 1024 + r) * HW + p0 + n0 + 2 * tg;
    #pragma unroll
    for (int i = 0; i < 4; i++) {
        const int mlo = m0 + 16 * i + g;
        float* prow = ob + (size_t)(8 * mlo) * HW;
        #pragma unroll
        for (int j = 0; j < 7; j++) {
            *(float2*)(prow + 8 * j) = make_float2(acc[i][j][0], acc[i][j][1]);
            *(float2*)(prow + (size_t)64 * HW + 8 * j) = make_float2(acc[i][j][2], acc[i][j][3]);
        }
    }
}

extern "C" void kernel_launch(void* const* d_in, const int* in_sizes, int n_in,
                              void* d_out, int out_size)
{
    const float* x = (const float*)d_in[0];
    const float* w = (const float*)d_in[1];
    float* out = (float*)d_out;

    scc_prep_w<<<512, 256>>>(w);   // 131072 threads: 1MB rounded+swizzled image

    cudaFuncSetAttribute(scc_mma_kernel,
                         cudaFuncAttributeMaxDynamicSharedMemorySize, SM_BYTES);
    dim3 grid(8, 14, 16);   // r fastest: adjacent groups share x channels in L2
    scc_mma_kernel<<<grid, 256, SM_BYTES>>>(x, out);
}

// round 15
// speedup vs baseline: 1.3839x; 1.3303x over previous
#include <cuda_runtime.h>
#include <cstdint>

#define HW    3136
#define CIN   1024
#define NT    224      // 14 * 224 = 3136 exactly
#define KC    32
#define NCH   8

// smem in 4B words: A: 2 buffers x 2048 words (8KB fp16 image per chunk)
//                   B: 2 buffers x 3600 words ([kstep 2][n 224][4 pairs] pitch 1800)
#define AWORDS   2048
#define BOFFW    (2 * AWORDS)          // 4096
#define BSTRIDE  1800                  // words per kstep (1792 + 8 pad, decollides s)
#define BWORDS   (2 * BSTRIDE)         // 3600
#define SMWORDS  (BOFFW + 2 * BWORDS)  // 11296
#define SMBYTES  (SMWORDS * 4)         // 45184

// fp16 weight image: [r(8)][ch(8)][s(2)][m(128)][pr(4)] of uint2
// uint2.x = half2(w[k+2pr], w[k+2pr+1]), .y = half2(w[k+2pr+8], w[k+2pr+9]), k = ch*32+16s
__device__ uint2 g_whf[65536];

static __device__ __forceinline__ uint32_t pack_h2(float hi, float lo) {
    uint32_t o;
    asm("cvt.rn.f16x2.f32 %0, %1, %2;" : "=r"(o) : "f"(hi), "f"(lo));
    return o;
}
static __device__ __forceinline__ uint32_t smem_u32(const void* p) {
    uint32_t a;
    asm("{\n\t.reg .u64 t;\n\tcvta.to.shared.u64 t, %1;\n\tcvt.u32.u64 %0, t;\n\t}"
        : "=r"(a) : "l"(p));
    return a;
}
static __device__ __forceinline__ void cp16(uint32_t dst, const void* src) {
    asm volatile("cp.async.cg.shared.global [%0], [%1], 16;" :: "r"(dst), "l"(src) : "memory");
}
static __device__ __forceinline__ void cp_commit() {
    asm volatile("cp.async.commit_group;" ::: "memory");
}
template <int N>
static __device__ __forceinline__ void cp_wait() {
    asm volatile("cp.async.wait_group %0;" :: "n"(N) : "memory");
}

// fp16 MMA, fp32 accumulate. a = {rowg_klo, rowg8_klo, rowg_khi, rowg8_khi}
static __device__ __forceinline__ void mma16(float* c,
    uint32_t a0, uint32_t a1, uint32_t a2, uint32_t a3, uint32_t b0, uint32_t b1) {
    asm volatile(
        "mma.sync.aligned.m16n8k16.row.col.f32.f16.f16.f32 "
        "{%0,%1,%2,%3}, {%4,%5,%6,%7}, {%8,%9}, {%0,%1,%2,%3};"
        : "+f"(c[0]), "+f"(c[1]), "+f"(c[2]), "+f"(c[3])
        : "r"(a0), "r"(a1), "r"(a2), "r"(a3), "r"(b0), "r"(b1));
}

// ---- prepass: w -> fp16 fragment-image ----
__global__ void scc_prep(const float* __restrict__ w)
{
    const int q = blockIdx.x * 256 + threadIdx.x;    // 0..65535
    const int pr = q & 3;
    const int m  = (q >> 2) & 127;
    const int s  = (q >> 9) & 1;
    const int ch = (q >> 10) & 7;
    const int r  = q >> 13;
    const float* row = w + (size_t)(r + 8 * m) * 256 + ch * 32 + 16 * s + 2 * pr;
    g_whf[q] = make_uint2(pack_h2(row[1], row[0]), pack_h2(row[9], row[8]));
}

__global__ __launch_bounds__(256, 1)
void scc_mma_kernel(const float* __restrict__ x,
                    float* __restrict__ out)
{
    extern __shared__ float sm[];
    const uint32_t sb = smem_u32(sm);
    const int tid = threadIdx.x;
    const int lid = tid & 31, wid = tid >> 5;
    const int g = lid >> 2, tg = lid & 3;
    const int r  = blockIdx.x;                  // group fastest: L2 x reuse
    const int p0 = blockIdx.y * NT;
    const int b  = blockIdx.z;
    const float* xb = x + (size_t)b * CIN * HW;

    // warp grid 2(M) x 4(N): warp tile 64 x 56
    const int m0 = (wid & 1) * 64;
    const int n0 = (wid >> 1) * 56;

    float acc[4][7][4];
    #pragma unroll
    for (int i = 0; i < 4; i++)
        #pragma unroll
        for (int j = 0; j < 7; j++)
            #pragma unroll
            for (int v = 0; v < 4; v++) acc[i][j][v] = 0.f;

    // ---- B loader roles: slot = tid + 256*it (it 0..1, it1 active if tid<192)
    // slot -> s = slot&1, pr = (slot>>1)&3, q = slot>>3 (0..55)
    const int bs0 = tid & 1,         bp0 = (tid >> 1) & 3,  bq0 = tid >> 3;
    const int sl1 = tid + 256;
    const int bs1 = sl1 & 1,         bp1 = (sl1 >> 1) & 3,  bq1 = sl1 >> 3;
    const bool act1 = (tid < 192);
    float4 breg[2][4];

    auto ISSUE_A = [&](int ch, int buf) {
        const char* src = (const char*)(g_whf + (size_t)(r * 8 + ch) * 1024);
        const uint32_t dst = sb + buf * (AWORDS * 4);
        cp16(dst + tid * 16,        src + tid * 16);
        cp16(dst + tid * 16 + 4096, src + tid * 16 + 4096);
        cp_commit();
    };
    auto LDG_B = [&](int ch) {
        const int cb = (r * 128 + ch * 32) & (CIN - 1);
        {
            const float* p = xb + (size_t)(cb + 16 * bs0 + 2 * bp0) * HW + p0 + 4 * bq0;
            breg[0][0] = *(const float4*)(p);
            breg[0][1] = *(const float4*)(p + (size_t)HW);
            breg[0][2] = *(const float4*)(p + (size_t)8 * HW);
            breg[0][3] = *(const float4*)(p + (size_t)9 * HW);
        }
        if (act1) {
            const float* p = xb + (size_t)(cb + 16 * bs1 + 2 * bp1) * HW + p0 + 4 * bq1;
            breg[1][0] = *(const float4*)(p);
            breg[1][1] = *(const float4*)(p + (size_t)HW);
            breg[1][2] = *(const float4*)(p + (size_t)8 * HW);
            breg[1][3] = *(const float4*)(p + (size_t)9 * HW);
        }
    };
    auto STS_B = [&](int buf) {
        uint2* bb = (uint2*)(sm + BOFFW + buf * BWORDS);
        {
            const float* v0 = &breg[0][0].x; const float* v1 = &breg[0][1].x;
            const float* v2 = &breg[0][2].x; const float* v3 = &breg[0][3].x;
            #pragma unroll
            for (int e = 0; e < 4; e++)
                bb[bs0 * 900 + (4 * bq0 + e) * 4 + bp0] =
                    make_uint2(pack_h2(v1[e], v0[e]), pack_h2(v3[e], v2[e]));
        }
        if (act1) {
            const float* v0 = &breg[1][0].x; const float* v1 = &breg[1][1].x;
            const float* v2 = &breg[1][2].x; const float* v3 = &breg[1][3].x;
            #pragma unroll
            for (int e = 0; e < 4; e++)
                bb[bs1 * 900 + (4 * bq1 + e) * 4 + bp1] =
                    make_uint2(pack_h2(v1[e], v0[e]), pack_h2(v3[e], v2[e]));
        }
    };

    auto COMPUTE = [&](int buf) {
        #pragma unroll
        for (int s = 0; s < 2; s++) {
            const uint2* Ab = (const uint2*)(sm + buf * AWORDS) + s * 512;
            const uint2* Bb = (const uint2*)(sm + BOFFW + buf * BWORDS) + s * 900;
            uint2 af[4][2];
            uint2 bf[7];
            #pragma unroll
            for (int i = 0; i < 4; i++) {
                af[i][0] = Ab[(m0 + 16 * i + g) * 4 + tg];
                af[i][1] = Ab[(m0 + 16 * i + g + 8) * 4 + tg];
            }
            #pragma unroll
            for (int j = 0; j < 7; j++)
                bf[j] = Bb[(n0 + 8 * j + g) * 4 + tg];
            #pragma unroll
            for (int i = 0; i < 4; i++)
                #pragma unroll
                for (int j = 0; j < 7; j++)
                    mma16(acc[i][j], af[i][0].x, af[i][1].x, af[i][0].y, af[i][1].y,
                          bf[j].x, bf[j].y);
        }
    };

    // ---- pipelined mainloop (R5 structure) ----
    ISSUE_A(0, 0);
    LDG_B(0);
    STS_B(0);
    cp_wait<0>();
    __syncthreads();

    #pragma unroll 1
    for (int ch = 0; ch < NCH; ch++) {
        const int buf = ch & 1;
        if (ch + 1 < NCH) {
            ISSUE_A(ch + 1, buf ^ 1);   // async A copy overlaps compute
            LDG_B(ch + 1);              // B global loads overlap compute
        }
        COMPUTE(buf);
        if (ch + 1 < NCH) {
            STS_B(buf ^ 1);
            cp_wait<0>();
            __syncthreads();
        }
    }

    // ---- epilogue: direct STG, float2 halves (full 32B sectors across quads) ----
    float* ob = out + ((size_t)b * 1024 + r) * HW + p0 + n0 + 2 * tg;
    #pragma unroll
    for (int i = 0; i < 4; i++) {
        const int mlo = m0 + 16 * i + g;
        float* prow = ob + (size_t)(8 * mlo) * HW;
        #pragma unroll
        for (int j = 0; j < 7; j++) {
            *(float2*)(prow + 8 * j) = make_float2(acc[i][j][0], acc[i][j][1]);
            *(float2*)(prow + (size_t)64 * HW + 8 * j) = make_float2(acc[i][j][2], acc[i][j][3]);
        }
    }
}

extern "C" void kernel_launch(void* const* d_in, const int* in_sizes, int n_in,
                              void* d_out, int out_size)
{
    const float* x = (const float*)d_in[0];
    const float* w = (const float*)d_in[1];
    float* out = (float*)d_out;

    scc_prep<<<256, 256>>>(w);   // 65536 threads: fp16 fragment image of w

    cudaFuncSetAttribute(scc_mma_kernel,
                         cudaFuncAttributeMaxDynamicSharedMemorySize, SMBYTES);
    dim3 grid(8, 14, 16);   // r fastest: adjacent groups share x channels in L2
    scc_mma_kernel<<<grid, 256, SMBYTES>>>(x, out);
}

// round 16
// speedup vs baseline: 1.8349x; 1.3258x over previous
#include <cuda_runtime.h>
#include <cstdint>

#define HW    3136
#define CIN   1024
#define NT    224      // 14 * 224 = 3136 exactly
#define KC    32
#define NCH   8

// smem words(4B): A: 2 x 2048 (8KB fp16 image/chunk)
//                 B: 2 x [32 k][pitch 228] fp32
#define AWORDS   2048
#define BOFFW    (2 * AWORDS)            // 4096
#define BPITCH   228                     // 2*228 mod 32 == 8 -> conflict-free frag rows
#define BWORDS   (KC * BPITCH)           // 7296
#define SMWORDS  (BOFFW + 2 * BWORDS)    // 18688
#define SMBYTES  (SMWORDS * 4)           // 74752

// fp16 weight image: [r(8)][ch(8)][s(2)][m(128)][pr(4)] of uint2
// uint2.x = half2(w[k+2pr+1], w[k+2pr]), .y = half2(w[k+2pr+9], w[k+2pr+8]), k = ch*32+16s
__device__ uint2 g_whf[65536];

static __device__ __forceinline__ uint32_t pack_h2(float hi, float lo) {
    uint32_t o;
    asm("cvt.rn.f16x2.f32 %0, %1, %2;" : "=r"(o) : "f"(hi), "f"(lo));
    return o;
}
static __device__ __forceinline__ uint32_t smem_u32(const void* p) {
    uint32_t a;
    asm("{\n\t.reg .u64 t;\n\tcvta.to.shared.u64 t, %1;\n\tcvt.u32.u64 %0, t;\n\t}"
        : "=r"(a) : "l"(p));
    return a;
}
static __device__ __forceinline__ void cp16(uint32_t dst, const void* src) {
    asm volatile("cp.async.cg.shared.global [%0], [%1], 16;" :: "r"(dst), "l"(src) : "memory");
}
static __device__ __forceinline__ void cp_commit() {
    asm volatile("cp.async.commit_group;" ::: "memory");
}
template <int N>
static __device__ __forceinline__ void cp_wait() {
    asm volatile("cp.async.wait_group %0;" :: "n"(N) : "memory");
}

static __device__ __forceinline__ void mma16(float* c,
    uint32_t a0, uint32_t a1, uint32_t a2, uint32_t a3, uint32_t b0, uint32_t b1) {
    asm volatile(
        "mma.sync.aligned.m16n8k16.row.col.f32.f16.f16.f32 "
        "{%0,%1,%2,%3}, {%4,%5,%6,%7}, {%8,%9}, {%0,%1,%2,%3};"
        : "+f"(c[0]), "+f"(c[1]), "+f"(c[2]), "+f"(c[3])
        : "r"(a0), "r"(a1), "r"(a2), "r"(a3), "r"(b0), "r"(b1));
}

// ---- prepass: w -> fp16 fragment-image (same layout as R15, verified) ----
__global__ void scc_prep(const float* __restrict__ w)
{
    const int q = blockIdx.x * 256 + threadIdx.x;    // 0..65535
    const int pr = q & 3;
    const int m  = (q >> 2) & 127;
    const int s  = (q >> 9) & 1;
    const int ch = (q >> 10) & 7;
    const int r  = q >> 13;
    const float* row = w + (size_t)(r + 8 * m) * 256 + ch * 32 + 16 * s + 2 * pr;
    g_whf[q] = make_uint2(pack_h2(row[1], row[0]), pack_h2(row[9], row[8]));
}

__global__ __launch_bounds__(256, 1)
void scc_mma_kernel(const float* __restrict__ x,
                    float* __restrict__ out)
{
    extern __shared__ float sm[];
    const uint32_t sb = smem_u32(sm);
    const int tid = threadIdx.x;
    const int lid = tid & 31, wid = tid >> 5;
    const int g = lid >> 2, tg = lid & 3;
    const int r  = blockIdx.x;                  // group fastest: L2 x reuse
    const int p0 = blockIdx.y * NT;
    const int b  = blockIdx.z;
    const float* xb = x + (size_t)b * CIN * HW;

    // warp grid 2(M) x 4(N): warp tile 64 x 56
    const int m0 = (wid & 1) * 64;
    const int n0 = (wid >> 1) * 56;

    float acc[4][7][4];
    #pragma unroll
    for (int i = 0; i < 4; i++)
        #pragma unroll
        for (int j = 0; j < 7; j++)
            #pragma unroll
            for (int v = 0; v < 4; v++) acc[i][j][v] = 0.f;

    // ---- chunk loader: A image copy (2 cp16) + coalesced B fp32 (7 cp16) ----
    auto ISSUE = [&](int ch, int buf) {
        const char* asrc = (const char*)(g_whf + (size_t)(r * 8 + ch) * 1024);
        const uint32_t adst = sb + buf * (AWORDS * 4);
        cp16(adst + tid * 16,        asrc + tid * 16);
        cp16(adst + tid * 16 + 4096, asrc + tid * 16 + 4096);

        const int c0 = (r * 128 + ch * KC) & (CIN - 1);
        const uint32_t bbase = sb + (BOFFW + buf * BWORDS) * 4;
        #pragma unroll
        for (int it = 0; it < 7; it++) {
            const int idx = tid + 256 * it;
            const int k = idx / 56, nq = idx % 56;
            cp16(bbase + (k * BPITCH + 4 * nq) * 4,
                 xb + (size_t)(c0 + k) * HW + p0 + 4 * nq);
        }
        cp_commit();
    };

    auto COMPUTE = [&](int buf) {
        #pragma unroll
        for (int s = 0; s < 2; s++) {
            const uint2* Ab = (const uint2*)(sm + buf * AWORDS) + s * 512;
            const float* Bb = sm + BOFFW + buf * BWORDS + (16 * s) * BPITCH;
            uint2 af[4][2];
            uint32_t bf[7][2];
            #pragma unroll
            for (int i = 0; i < 4; i++) {
                af[i][0] = Ab[(m0 + 16 * i + g) * 4 + tg];
                af[i][1] = Ab[(m0 + 16 * i + g + 8) * 4 + tg];
            }
            #pragma unroll
            for (int j = 0; j < 7; j++) {
                const int n = n0 + 8 * j + g;
                const float* col = Bb + 2 * tg * BPITCH + n;
                const float v0 = col[0];
                const float v1 = col[BPITCH];
                const float v2 = col[8 * BPITCH];
                const float v3 = col[9 * BPITCH];
                bf[j][0] = pack_h2(v1, v0);
                bf[j][1] = pack_h2(v3, v2);
            }
            #pragma unroll
            for (int i = 0; i < 4; i++)
                #pragma unroll
                for (int j = 0; j < 7; j++)
                    mma16(acc[i][j], af[i][0].x, af[i][1].x, af[i][0].y, af[i][1].y,
                          bf[j][0], bf[j][1]);
        }
    };

    // ---- pipelined mainloop (R5 structure) ----
    ISSUE(0, 0);
    cp_wait<0>();
    __syncthreads();

    #pragma unroll 1
    for (int ch = 0; ch < NCH; ch++) {
        const int buf = ch & 1;
        if (ch + 1 < NCH) ISSUE(ch + 1, buf ^ 1);   // async, overlaps compute
        COMPUTE(buf);
        if (ch + 1 < NCH) {
            cp_wait<0>();
            __syncthreads();
        }
    }

    // ---- epilogue: direct STG, float2 halves (full 32B sectors across quads) ----
    float* ob = out + ((size_t)b * 1024 + r) * HW + p0 + n0 + 2 * tg;
    #pragma unroll
    for (int i = 0; i < 4; i++) {
        const int mlo = m0 + 16 * i + g;
        float* prow = ob + (size_t)(8 * mlo) * HW;
        #pragma unroll
        for (int j = 0; j < 7; j++) {
            *(float2*)(prow + 8 * j) = make_float2(acc[i][j][0], acc[i][j][1]);
            *(float2*)(prow + (size_t)64 * HW + 8 * j) = make_float2(acc[i][j][2], acc[i][j][3]);
        }
    }
}

extern "C" void kernel_launch(void* const* d_in, const int* in_sizes, int n_in,
                              void* d_out, int out_size)
{
    const float* x = (const float*)d_in[0];
    const float* w = (const float*)d_in[1];
    float* out = (float*)d_out;

    scc_prep<<<256, 256>>>(w);   // fp16 fragment image of w

    cudaFuncSetAttribute(scc_mma_kernel,
                         cudaFuncAttributeMaxDynamicSharedMemorySize, SMBYTES);
    dim3 grid(8, 14, 16);   // r fastest: adjacent groups share x channels in L2
    scc_mma_kernel<<<grid, 256, SMBYTES>>>(x, out);
}

// round 17
// speedup vs baseline: 2.0985x; 1.1437x over previous
#include <cuda_runtime.h>
#include <cstdint>

#define HW    3136
#define CIN   1024
#define NT    112      // 28 * 112 = 3136 exactly
#define KC    32
#define NCH   8

// per-CTA smem words(4B): A: 2 x 2048 (8KB fp16 image/chunk)
//                         B: 2 x [32 k][pitch 116] fp32
#define AWORDS   2048
#define BOFFW    (2 * AWORDS)            // 4096
#define BPITCH   116                     // 2*116 mod 32 == 8 -> conflict-free frag rows
#define BWORDS   (KC * BPITCH)           // 3712
#define SMWORDS  (BOFFW + 2 * BWORDS)    // 11520
#define SMBYTES  (SMWORDS * 4)           // 46080 -> 2 CTAs fit in 228KB

// fp16 weight image: [r(8)][ch(8)][s(2)][m(128)][pr(4)] of uint2
// uint2.x = half2(w[k+2pr+1], w[k+2pr]), .y = half2(w[k+2pr+9], w[k+2pr+8]), k = ch*32+16s
__device__ uint2 g_whf[65536];

static __device__ __forceinline__ uint32_t pack_h2(float hi, float lo) {
    uint32_t o;
    asm("cvt.rn.f16x2.f32 %0, %1, %2;" : "=r"(o) : "f"(hi), "f"(lo));
    return o;
}
static __device__ __forceinline__ uint32_t smem_u32(const void* p) {
    uint32_t a;
    asm("{\n\t.reg .u64 t;\n\tcvta.to.shared.u64 t, %1;\n\tcvt.u32.u64 %0, t;\n\t}"
        : "=r"(a) : "l"(p));
    return a;
}
static __device__ __forceinline__ void cp16(uint32_t dst, const void* src) {
    asm volatile("cp.async.cg.shared.global [%0], [%1], 16;" :: "r"(dst), "l"(src) : "memory");
}
static __device__ __forceinline__ void cp_commit() {
    asm volatile("cp.async.commit_group;" ::: "memory");
}
template <int N>
static __device__ __forceinline__ void cp_wait() {
    asm volatile("cp.async.wait_group %0;" :: "n"(N) : "memory");
}

static __device__ __forceinline__ void mma16(float* c,
    uint32_t a0, uint32_t a1, uint32_t a2, uint32_t a3, uint32_t b0, uint32_t b1) {
    asm volatile(
        "mma.sync.aligned.m16n8k16.row.col.f32.f16.f16.f32 "
        "{%0,%1,%2,%3}, {%4,%5,%6,%7}, {%8,%9}, {%0,%1,%2,%3};"
        : "+f"(c[0]), "+f"(c[1]), "+f"(c[2]), "+f"(c[3])
        : "r"(a0), "r"(a1), "r"(a2), "r"(a3), "r"(b0), "r"(b1));
}

// ---- prepass: w -> fp16 fragment-image (layout verified in R15/R16) ----
__global__ void scc_prep(const float* __restrict__ w)
{
    const int q = blockIdx.x * 256 + threadIdx.x;    // 0..65535
    const int pr = q & 3;
    const int m  = (q >> 2) & 127;
    const int s  = (q >> 9) & 1;
    const int ch = (q >> 10) & 7;
    const int r  = q >> 13;
    const float* row = w + (size_t)(r + 8 * m) * 256 + ch * 32 + 16 * s + 2 * pr;
    g_whf[q] = make_uint2(pack_h2(row[1], row[0]), pack_h2(row[9], row[8]));
}

__global__ __launch_bounds__(128, 2)
void scc_mma_kernel(const float* __restrict__ x,
                    float* __restrict__ out)
{
    extern __shared__ float sm[];
    const uint32_t sb = smem_u32(sm);
    const int tid = threadIdx.x;
    const int lid = tid & 31, wid = tid >> 5;   // 4 warps
    const int g = lid >> 2, tg = lid & 3;
    const int r  = blockIdx.x;                  // group fastest: L2 x reuse
    const int p0 = blockIdx.y * NT;
    const int b  = blockIdx.z;
    const float* xb = x + (size_t)b * CIN * HW;

    // warp grid 2(M) x 2(N): warp tile 64 x 56 over CTA tile 128 x 112
    const int m0 = (wid & 1) * 64;
    const int n0 = (wid >> 1) * 56;

    float acc[4][7][4];
    #pragma unroll
    for (int i = 0; i < 4; i++)
        #pragma unroll
        for (int j = 0; j < 7; j++)
            #pragma unroll
            for (int v = 0; v < 4; v++) acc[i][j][v] = 0.f;

    // ---- chunk loader: A image copy (4 cp16) + coalesced B fp32 (7 cp16) ----
    auto ISSUE = [&](int ch, int buf) {
        const char* asrc = (const char*)(g_whf + (size_t)(r * 8 + ch) * 1024);
        const uint32_t adst = sb + buf * (AWORDS * 4);
        #pragma unroll
        for (int it = 0; it < 4; it++)
            cp16(adst + tid * 16 + it * 2048, asrc + tid * 16 + it * 2048);

        const int c0 = (r * 128 + ch * KC) & (CIN - 1);
        const uint32_t bbase = sb + (BOFFW + buf * BWORDS) * 4;
        #pragma unroll
        for (int it = 0; it < 7; it++) {
            const int idx = tid + 128 * it;
            const int k = idx / 28, nq = idx % 28;
            cp16(bbase + (k * BPITCH + 4 * nq) * 4,
                 xb + (size_t)(c0 + k) * HW + p0 + 4 * nq);
        }
        cp_commit();
    };

    auto COMPUTE = [&](int buf) {
        #pragma unroll
        for (int s = 0; s < 2; s++) {
            const uint2* Ab = (const uint2*)(sm + buf * AWORDS) + s * 512;
            const float* Bb = sm + BOFFW + buf * BWORDS + (16 * s) * BPITCH;
            uint2 af[4][2];
            uint32_t bf[7][2];
            #pragma unroll
            for (int i = 0; i < 4; i++) {
                af[i][0] = Ab[(m0 + 16 * i + g) * 4 + tg];
                af[i][1] = Ab[(m0 + 16 * i + g + 8) * 4 + tg];
            }
            #pragma unroll
            for (int j = 0; j < 7; j++) {
                const int n = n0 + 8 * j + g;
                const float* col = Bb + 2 * tg * BPITCH + n;
                const float v0 = col[0];
                const float v1 = col[BPITCH];
                const float v2 = col[8 * BPITCH];
                const float v3 = col[9 * BPITCH];
                bf[j][0] = pack_h2(v1, v0);
                bf[j][1] = pack_h2(v3, v2);
            }
            #pragma unroll
            for (int i = 0; i < 4; i++)
                #pragma unroll
                for (int j = 0; j < 7; j++)
                    mma16(acc[i][j], af[i][0].x, af[i][1].x, af[i][0].y, af[i][1].y,
                          bf[j][0], bf[j][1]);
        }
    };

    // ---- pipelined mainloop (R5 structure) ----
    ISSUE(0, 0);
    cp_wait<0>();
    __syncthreads();

    #pragma unroll 1
    for (int ch = 0; ch < NCH; ch++) {
        const int buf = ch & 1;
        if (ch + 1 < NCH) ISSUE(ch + 1, buf ^ 1);   // async, overlaps compute
        COMPUTE(buf);
        if (ch + 1 < NCH) {
            cp_wait<0>();
            __syncthreads();
        }
    }

    // ---- epilogue: direct STG, float2 halves (full 32B sectors across quads) ----
    float* ob = out + ((size_t)b * 1024 + r) * HW + p0 + n0 + 2 * tg;
    #pragma unroll
    for (int i = 0; i < 4; i++) {
        const int mlo = m0 + 16 * i + g;
        float* prow = ob + (size_t)(8 * mlo) * HW;
        #pragma unroll
        for (int j = 0; j < 7; j++) {
            *(float2*)(prow + 8 * j) = make_float2(acc[i][j][0], acc[i][j][1]);
            *(float2*)(prow + (size_t)64 * HW + 8 * j) = make_float2(acc[i][j][2], acc[i][j][3]);
        }
    }
}

extern "C" void kernel_launch(void* const* d_in, const int* in_sizes, int n_in,
                              void* d_out, int out_size)
{
    const float* x = (const float*)d_in[0];
    const float* w = (const float*)d_in[1];
    float* out = (float*)d_out;

    scc_prep<<<256, 256>>>(w);   // fp16 fragment image of w

    cudaFuncSetAttribute(scc_mma_kernel,
                         cudaFuncAttributeMaxDynamicSharedMemorySize, SMBYTES);
    dim3 grid(8, 28, 16);   // 3584 CTAs, 2 per SM; r fastest for L2 x reuse
    scc_mma_kernel<<<grid, 128, SMBYTES>>>(x, out);
}